// round 5
// baseline (speedup 1.0000x reference)
#include <cuda_runtime.h>
#include <cuda_fp16.h>
#include <cstdint>

// ---------------- problem constants ----------------
#define HDIM   4096
#define MTOT   16384
#define NGRP   8
#define I2     3072
#define IHALF  1536
#define MSPLIT 2048

// ---------------- GEMM tiling ----------------
#define BM      128
#define BN      128
#define KC      64              // fp16 elems per K chunk (128 B rows)
#define NSTAGE  4
#define KITERS  (HDIM / KC)     // 64 iters per tile
#define NTILES  (NGRP * (MSPLIT / BM) * (IHALF / BN))  // 1536

#define NTHREADS 320            // 8 consumer warps + 2 producer warps
#define NCONS    256
#define NPROD    64

#define A_BYTES     (BM * KC * 2)              // 16384
#define B_BYTES     (BN * KC * 2)              // 16384
#define STAGE_BYTES (A_BYTES + 2 * B_BYTES)    // 49152

// SMEM: [0:32) full mbarriers, [32:64) empty mbarriers, [1024:...) stages
#define OFF_FULL   0
#define OFF_EMPTY  32
#define OFF_TILES  1024
#define SMEM_BYTES (OFF_TILES + NSTAGE * STAGE_BYTES)   // 197632

// ---------------- fp16 scratch (device globals; no allocation) ----------------
__device__ __align__(1024) __half g_xh[(size_t)MTOT * HDIM];
__device__ __align__(1024) __half g_wh[(size_t)NGRP * I2 * HDIM];

#define N4X ((MTOT * HDIM) / 4)
#define N4W ((NGRP * I2 * HDIM) / 4)

// ---------------- helpers ----------------
__device__ __forceinline__ uint32_t smem_u32(const void* p) {
    uint32_t a;
    asm("{ .reg .u64 t; cvta.to.shared.u64 t, %1; cvt.u32.u64 %0, t; }" : "=r"(a) : "l"(p));
    return a;
}
__device__ __forceinline__ uint32_t swz(uint32_t o) {
    return o ^ ((o >> 3) & 0x70);
}
__device__ __forceinline__ void cp16(uint32_t s, const void* g) {
    asm volatile("cp.async.cg.shared.global [%0], [%1], 16;" :: "r"(s), "l"(g));
}
__device__ __forceinline__ void cp_commit() {
    asm volatile("cp.async.commit_group;" ::: "memory");
}
template <int N>
__device__ __forceinline__ void cp_wait() {
    asm volatile("cp.async.wait_group %0;" :: "n"(N) : "memory");
}
#define MBARRIER_INIT(addr, cnt) \
    asm volatile("mbarrier.init.shared.b64 [%0], %1;" :: "r"(addr), "r"(cnt) : "memory")
#define MBARRIER_ARRIVE(addr) \
    asm volatile("mbarrier.arrive.shared.b64 _, [%0];" :: "r"(addr) : "memory")
__device__ __forceinline__ void mbar_wait(uint32_t mbar, uint32_t parity) {
    asm volatile(
        "{\n\t.reg .pred P;\n\t"
        "W_%=:\n\t"
        "mbarrier.try_wait.parity.acquire.cta.shared::cta.b64 P, [%0], %1, 0x989680;\n\t"
        "@!P bra W_%=;\n\t}"
        :: "r"(mbar), "r"(parity) : "memory");
}
__device__ __forceinline__ void ldmx4(uint32_t& r0, uint32_t& r1, uint32_t& r2, uint32_t& r3,
                                      uint32_t addr) {
    asm volatile("ldmatrix.sync.aligned.m8n8.x4.shared.b16 {%0,%1,%2,%3}, [%4];"
                 : "=r"(r0), "=r"(r1), "=r"(r2), "=r"(r3) : "r"(addr));
}
__device__ __forceinline__ void mma16816(float* c, const uint32_t* a, const uint32_t* b) {
    asm volatile(
        "mma.sync.aligned.m16n8k16.row.col.f32.f16.f16.f32 "
        "{%0,%1,%2,%3}, {%4,%5,%6,%7}, {%8,%9}, {%0,%1,%2,%3};"
        : "+f"(c[0]), "+f"(c[1]), "+f"(c[2]), "+f"(c[3])
        : "r"(a[0]), "r"(a[1]), "r"(a[2]), "r"(a[3]), "r"(b[0]), "r"(b[1]));
}

// ---------------- fp32 -> fp16 convert (x and w in ONE launch) ----------------
__global__ void cvt_all_f16(const float4* __restrict__ x, const float4* __restrict__ w,
                            uint2* __restrict__ xh, uint2* __restrict__ wh) {
    int i = blockIdx.x * blockDim.x + threadIdx.x;
    const float4* in;
    uint2* out;
    int j;
    if (i < N4X) { in = x; out = xh; j = i; }
    else         { in = w; out = wh; j = i - N4X; if (j >= N4W) return; }
    float4 v = in[j];
    __half2 h0 = __floats2half2_rn(v.x, v.y);
    __half2 h1 = __floats2half2_rn(v.z, v.w);
    uint2 u;
    u.x = *reinterpret_cast<uint32_t*>(&h0);
    u.y = *reinterpret_cast<uint32_t*>(&h1);
    out[j] = u;
}

// ---------------- persistent warp-specialized GEMM + SwiGLU ----------------
// Warps 0-7: consumers (warptile 64x32, gate+up accumulators).
// Warps 8-9: producers (cp.async only; all tile-index math lives here).
__global__ void __launch_bounds__(NTHREADS, 1)
teswiglu_gemm(const __half* __restrict__ xh, const __half* __restrict__ wh,
              float* __restrict__ out) {
    extern __shared__ __align__(1024) char smem[];
    uint32_t sbase = smem_u32(smem);
    const int tid = threadIdx.x;
    const int wid = tid >> 5;
    const int lid = tid & 31;
    const int bid = blockIdx.x;
    const int nct = gridDim.x;

    const int my_ntiles = (NTILES - bid + nct - 1) / nct;
    const int total = my_ntiles * KITERS;

    if (tid == 0) {
        #pragma unroll
        for (int s = 0; s < NSTAGE; s++) {
            MBARRIER_INIT(sbase + OFF_FULL + s * 8, 2);   // 2 producer warps
            MBARRIER_INIT(sbase + OFF_EMPTY + s * 8, 8);  // 8 consumer warps
        }
    }
    __syncthreads();

    if (wid >= 8) {
        // ================= PRODUCER =================
        const int ptid = tid - NCONS;  // 0..63
        const __half* Ag = nullptr;
        const __half* Bg = nullptr;
        const __half* Bu = nullptr;

        for (int lit = 0; lit < total; lit++) {
            if ((lit & 63) == 0) {
                int tile = bid + nct * (lit >> 6);
                int nt = tile % 12;
                int rem = tile / 12;
                int mt = rem & 15;
                int g = rem >> 4;
                Ag = xh + (size_t)(g * MSPLIT + mt * BM) * HDIM;
                Bg = wh + ((size_t)g * I2 + nt * BN) * HDIM;
                Bu = Bg + (size_t)IHALF * HDIM;
            }
            int s = lit & 3;
            int r = lit >> 2;
            if (r >= 1) mbar_wait(sbase + OFF_EMPTY + s * 8, (uint32_t)((r - 1) & 1));

            int k0 = (lit & 63) * KC;
            uint32_t st = sbase + OFF_TILES + s * STAGE_BYTES;
            #pragma unroll
            for (int c = 0; c < 16; c++) {
                int idx = ptid + c * NPROD;
                int row = idx >> 3, seg = idx & 7;
                cp16(st + swz(row * 128 + seg * 16), Ag + (size_t)row * HDIM + k0 + seg * 8);
            }
            #pragma unroll
            for (int c = 0; c < 16; c++) {
                int idx = ptid + c * NPROD;
                int row = idx >> 3, seg = idx & 7;
                uint32_t so = swz(row * 128 + seg * 16);
                const size_t go = (size_t)row * HDIM + k0 + seg * 8;
                cp16(st + A_BYTES + so, Bg + go);
                cp16(st + A_BYTES + B_BYTES + so, Bu + go);
            }
            cp_commit();

            if (lit >= 2) {
                cp_wait<2>();
                if (lid == 0) MBARRIER_ARRIVE(sbase + OFF_FULL + ((lit - 2) & 3) * 8);
            }
        }
        // drain last two groups
        cp_wait<1>();
        if (lid == 0) MBARRIER_ARRIVE(sbase + OFF_FULL + ((total - 2) & 3) * 8);
        cp_wait<0>();
        if (lid == 0) MBARRIER_ARRIVE(sbase + OFF_FULL + ((total - 1) & 3) * 8);
    } else {
        // ================= CONSUMER =================
        const int wm = wid >> 2;      // 0..1 (64-row slabs)
        const int wn = wid & 3;       // 0..3 (32-col slabs)

        float cg[4][4][4];
        float cu[4][4][4];

        const int la_row = (lid & 7) + ((lid >> 3) & 1) * 8;
        const int la_kb  = ((lid >> 4) & 1) * 16;
        const int lb_row = (lid & 7) + ((lid >> 4) & 1) * 8;
        const int lb_kb  = ((lid >> 3) & 1) * 16;

        for (int it = 0; it < total; it++) {
            if ((it & 63) == 0) {
                #pragma unroll
                for (int a = 0; a < 4; a++)
                    #pragma unroll
                    for (int b = 0; b < 4; b++)
                        #pragma unroll
                        for (int q = 0; q < 4; q++) { cg[a][b][q] = 0.f; cu[a][b][q] = 0.f; }
            }
            int s = it & 3;
            int r = it >> 2;
            mbar_wait(sbase + OFF_FULL + s * 8, (uint32_t)(r & 1));

            uint32_t st = sbase + OFF_TILES + s * STAGE_BYTES;
            uint32_t sA = st;
            uint32_t sBg = st + A_BYTES;
            uint32_t sBu = st + A_BYTES + B_BYTES;

            #pragma unroll
            for (int ki = 0; ki < 4; ki++) {
                uint32_t bg[4][2], bu[4][2];
                #pragma unroll
                for (int nj = 0; nj < 2; nj++) {
                    int row = wn * 32 + nj * 16 + lb_row;
                    uint32_t off = swz(row * 128 + ki * 32 + lb_kb);
                    ldmx4(bg[2 * nj][0], bg[2 * nj][1], bg[2 * nj + 1][0], bg[2 * nj + 1][1],
                          sBg + off);
                    ldmx4(bu[2 * nj][0], bu[2 * nj][1], bu[2 * nj + 1][0], bu[2 * nj + 1][1],
                          sBu + off);
                }
                #pragma unroll
                for (int mi = 0; mi < 4; mi++) {
                    uint32_t a[4];
                    int row = wm * 64 + mi * 16 + la_row;
                    ldmx4(a[0], a[1], a[2], a[3], sA + swz(row * 128 + ki * 32 + la_kb));
                    #pragma unroll
                    for (int f = 0; f < 4; f++) {
                        mma16816(cg[mi][f], a, bg[f]);
                        mma16816(cu[mi][f], a, bu[f]);
                    }
                }
            }

            if (lid == 0) MBARRIER_ARRIVE(sbase + OFF_EMPTY + s * 8);

            // ---- epilogue at tile end (next tile's loads continue in background) ----
            if ((it & 63) == 63) {
                int tile = bid + nct * (it >> 6);
                int nt = tile % 12;
                int rem = tile / 12;
                int mt = rem & 15;
                int g = rem >> 4;
                int m0 = g * MSPLIT + mt * BM;
                #pragma unroll
                for (int mi = 0; mi < 4; mi++) {
                    #pragma unroll
                    for (int f = 0; f < 4; f++) {
                        int row = m0 + wm * 64 + mi * 16 + (lid >> 2);
                        int col = nt * BN + wn * 32 + f * 8 + 2 * (lid & 3);
                        float o[4];
                        #pragma unroll
                        for (int q = 0; q < 4; q++) {
                            float gv = cg[mi][f][q];
                            float uv = cu[mi][f][q];
                            o[q] = gv / (1.0f + __expf(-gv)) * uv;
                        }
                        *reinterpret_cast<float2*>(out + (size_t)row * IHALF + col) =
                            make_float2(o[0], o[1]);
                        *reinterpret_cast<float2*>(out + (size_t)(row + 8) * IHALF + col) =
                            make_float2(o[2], o[3]);
                    }
                }
            }
        }
    }
}

// ---------------- host launch ----------------
extern "C" void kernel_launch(void* const* d_in, const int* in_sizes, int n_in,
                              void* d_out, int out_size) {
    const float* x = (const float*)d_in[0];
    const float* w = (const float*)d_in[1];
    float* out = (float*)d_out;

    void* xh_ptr = nullptr;
    void* wh_ptr = nullptr;
    cudaGetSymbolAddress(&xh_ptr, g_xh);
    cudaGetSymbolAddress(&wh_ptr, g_wh);

    {
        int n4 = N4X + N4W;
        cvt_all_f16<<<n4 / 256, 256>>>((const float4*)x, (const float4*)w,
                                       (uint2*)xh_ptr, (uint2*)wh_ptr);
    }

    static int nsm = 0;
    if (nsm == 0) {
        cudaDeviceGetAttribute(&nsm, cudaDevAttrMultiProcessorCount, 0);
        if (nsm <= 0) nsm = 148;
    }

    cudaFuncSetAttribute(teswiglu_gemm, cudaFuncAttributeMaxDynamicSharedMemorySize, SMEM_BYTES);
    teswiglu_gemm<<<nsm, NTHREADS, SMEM_BYTES>>>((const __half*)xh_ptr, (const __half*)wh_ptr, out);
}

// round 6
// speedup vs baseline: 1.0691x; 1.0691x over previous
#include <cuda_runtime.h>
#include <cuda_fp16.h>
#include <cstdint>

// ---------------- problem constants ----------------
#define HDIM   4096
#define MTOT   16384
#define NGRP   8
#define I2     3072
#define IHALF  1536
#define MSPLIT 2048

// ---------------- GEMM tiling ----------------
#define BM      128
#define BN      128
#define KC      64              // fp16 elems per K chunk (128 B rows)
#define NSTAGE  4
#define NITER   (HDIM / KC)     // 64

#define A_BYTES     (BM * KC * 2)              // 16384
#define B_BYTES     (BN * KC * 2)              // 16384
#define STAGE_BYTES (A_BYTES + 2 * B_BYTES)    // 49152
#define SMEM_BYTES  (NSTAGE * STAGE_BYTES)     // 196608

// ---------------- fp16 scratch (device globals; no allocation) ----------------
__device__ __align__(1024) __half g_xh[(size_t)MTOT * HDIM];
__device__ __align__(1024) __half g_wh[(size_t)NGRP * I2 * HDIM];

#define N8X ((MTOT * HDIM) / 8)            // 8388608
#define N8W ((NGRP * I2 * HDIM) / 8)       // 12582912

// ---------------- helpers ----------------
__device__ __forceinline__ uint32_t smem_u32(const void* p) {
    uint32_t a;
    asm("{ .reg .u64 t; cvta.to.shared.u64 t, %1; cvt.u32.u64 %0, t; }" : "=r"(a) : "l"(p));
    return a;
}
__device__ __forceinline__ uint32_t swz(uint32_t o) {
    return o ^ ((o >> 3) & 0x70);
}
__device__ __forceinline__ void cp16(uint32_t s, const void* g) {
    asm volatile("cp.async.cg.shared.global [%0], [%1], 16;" :: "r"(s), "l"(g));
}
__device__ __forceinline__ void cp_commit() {
    asm volatile("cp.async.commit_group;" ::: "memory");
}
template <int N>
__device__ __forceinline__ void cp_wait() {
    asm volatile("cp.async.wait_group %0;" :: "n"(N) : "memory");
}
__device__ __forceinline__ void ldmx4(uint32_t* r, uint32_t addr) {
    asm volatile("ldmatrix.sync.aligned.m8n8.x4.shared.b16 {%0,%1,%2,%3}, [%4];"
                 : "=r"(r[0]), "=r"(r[1]), "=r"(r[2]), "=r"(r[3]) : "r"(addr));
}
__device__ __forceinline__ void mma16816(float* c, const uint32_t* a, const uint32_t* b) {
    asm volatile(
        "mma.sync.aligned.m16n8k16.row.col.f32.f16.f16.f32 "
        "{%0,%1,%2,%3}, {%4,%5,%6,%7}, {%8,%9}, {%0,%1,%2,%3};"
        : "+f"(c[0]), "+f"(c[1]), "+f"(c[2]), "+f"(c[3])
        : "r"(a[0]), "r"(a[1]), "r"(a[2]), "r"(a[3]), "r"(b[0]), "r"(b[1]));
}
__device__ __forceinline__ void stg_cs_f2(float* p, float a, float b) {
    asm volatile("st.global.cs.v2.f32 [%0], {%1,%2};" :: "l"(p), "f"(a), "f"(b) : "memory");
}

// ---------------- fp32 -> fp16 convert (x and w, streaming, 8 elems/thread) ----------------
__global__ void cvt_all_f16(const float4* __restrict__ x, const float4* __restrict__ w,
                            uint4* __restrict__ xh, uint4* __restrict__ wh) {
    int i = blockIdx.x * blockDim.x + threadIdx.x;
    const float4* in;
    uint4* out;
    int j;
    if (i < N8X) { in = x; out = xh; j = i; }
    else         { in = w; out = wh; j = i - N8X; if (j >= N8W) return; }
    float4 v0 = __ldcs(in + 2 * (size_t)j);
    float4 v1 = __ldcs(in + 2 * (size_t)j + 1);
    __half2 h0 = __floats2half2_rn(v0.x, v0.y);
    __half2 h1 = __floats2half2_rn(v0.z, v0.w);
    __half2 h2 = __floats2half2_rn(v1.x, v1.y);
    __half2 h3 = __floats2half2_rn(v1.z, v1.w);
    uint4 u;
    u.x = *reinterpret_cast<uint32_t*>(&h0);
    u.y = *reinterpret_cast<uint32_t*>(&h1);
    u.z = *reinterpret_cast<uint32_t*>(&h2);
    u.w = *reinterpret_cast<uint32_t*>(&h3);
    __stcs(out + j, u);
}

// ---------------- fused GEMM + SwiGLU (R2 architecture + frag double-buffer) ----------------
// CTA tile: 128 rows x 128 output cols; computes gate AND up for those cols.
// 8 warps: wm = wid>>2 (2 x 64 rows), wn = wid&3 (4 x 32 cols).
__global__ void __launch_bounds__(256, 1)
teswiglu_gemm(const __half* __restrict__ xh, const __half* __restrict__ wh,
              float* __restrict__ out) {
    extern __shared__ __align__(128) char smem[];
    uint32_t sbase = smem_u32(smem);
    int tid = threadIdx.x;
    int wid = tid >> 5;
    int lid = tid & 31;

    int bid = blockIdx.x;
    int nt = bid % (IHALF / BN);                    // 12
    int mt = (bid / (IHALF / BN)) % (MSPLIT / BM);  // 16
    int g  = bid / ((IHALF / BN) * (MSPLIT / BM));

    const int m0 = g * MSPLIT + mt * BM;
    const __half* Ag = xh + (size_t)m0 * HDIM;
    const __half* Bg = wh + ((size_t)g * I2 + nt * BN) * HDIM;
    const __half* Bu = Bg + (size_t)IHALF * HDIM;

    auto load_stage = [&](int s, int k0) {
        uint32_t st = sbase + s * STAGE_BYTES;
        #pragma unroll
        for (int c = 0; c < 4; c++) {
            int idx = tid + c * 256;
            int row = idx >> 3, seg = idx & 7;
            cp16(st + swz(row * 128 + seg * 16), Ag + (size_t)row * HDIM + k0 + seg * 8);
        }
        #pragma unroll
        for (int c = 0; c < 4; c++) {
            int idx = tid + c * 256;
            int row = idx >> 3, seg = idx & 7;
            uint32_t so = swz(row * 128 + seg * 16);
            const size_t go = (size_t)row * HDIM + k0 + seg * 8;
            cp16(st + A_BYTES + so, Bg + go);
            cp16(st + A_BYTES + B_BYTES + so, Bu + go);
        }
        cp_commit();
    };

    #pragma unroll
    for (int s = 0; s < NSTAGE - 1; s++) load_stage(s, s * KC);

    const int wm = wid >> 2;      // 0..1 (64-row slabs)
    const int wn = wid & 3;       // 0..3 (32-col slabs)

    float cg[4][4][4];
    float cu[4][4][4];
    #pragma unroll
    for (int a = 0; a < 4; a++)
        #pragma unroll
        for (int b = 0; b < 4; b++)
            #pragma unroll
            for (int q = 0; q < 4; q++) { cg[a][b][q] = 0.f; cu[a][b][q] = 0.f; }

    const int la_row = (lid & 7) + ((lid >> 3) & 1) * 8;
    const int la_kb  = ((lid >> 4) & 1) * 16;
    const int lb_row = (lid & 7) + ((lid >> 4) & 1) * 8;
    const int lb_kb  = ((lid >> 3) & 1) * 16;

    // fragment double buffers
    uint32_t af[2][4][4];
    uint32_t bgf[2][4][2], buf_[2][4][2];

    for (int it = 0; it < NITER; it++) {
        cp_wait<NSTAGE - 2>();
        __syncthreads();
        int jn = it + NSTAGE - 1;
        if (jn < NITER) load_stage(jn % NSTAGE, jn * KC);

        uint32_t st = sbase + (it % NSTAGE) * STAGE_BYTES;
        uint32_t sA = st;
        uint32_t sBg = st + A_BYTES;
        uint32_t sBu = st + A_BYTES + B_BYTES;

        // fragment loads for one ki into buffer b
        auto ld_frags = [&](int ki, int b) {
            #pragma unroll
            for (int mi = 0; mi < 4; mi++) {
                int row = wm * 64 + mi * 16 + la_row;
                ldmx4(af[b][mi], sA + swz(row * 128 + ki * 32 + la_kb));
            }
            #pragma unroll
            for (int nj = 0; nj < 2; nj++) {
                int row = wn * 32 + nj * 16 + lb_row;
                uint32_t off = swz(row * 128 + ki * 32 + lb_kb);
                uint32_t t0[4], t1[4];
                ldmx4(t0, sBg + off);
                ldmx4(t1, sBu + off);
                bgf[b][2 * nj][0] = t0[0]; bgf[b][2 * nj][1] = t0[1];
                bgf[b][2 * nj + 1][0] = t0[2]; bgf[b][2 * nj + 1][1] = t0[3];
                buf_[b][2 * nj][0] = t1[0]; buf_[b][2 * nj][1] = t1[1];
                buf_[b][2 * nj + 1][0] = t1[2]; buf_[b][2 * nj + 1][1] = t1[3];
            }
        };

        ld_frags(0, 0);
        #pragma unroll
        for (int ki = 0; ki < 4; ki++) {
            int cur = ki & 1;
            if (ki < 3) ld_frags(ki + 1, cur ^ 1);
            #pragma unroll
            for (int mi = 0; mi < 4; mi++) {
                #pragma unroll
                for (int f = 0; f < 4; f++) {
                    mma16816(cg[mi][f], af[cur][mi], bgf[cur][f]);
                    mma16816(cu[mi][f], af[cur][mi], buf_[cur][f]);
                }
            }
        }
    }

    // ---- epilogue: silu(gate) * up, streaming fp32 stores ----
    #pragma unroll
    for (int mi = 0; mi < 4; mi++) {
        #pragma unroll
        for (int f = 0; f < 4; f++) {
            int row = m0 + wm * 64 + mi * 16 + (lid >> 2);
            int col = nt * BN + wn * 32 + f * 8 + 2 * (lid & 3);
            float o[4];
            #pragma unroll
            for (int q = 0; q < 4; q++) {
                float gv = cg[mi][f][q];
                float uv = cu[mi][f][q];
                o[q] = gv / (1.0f + __expf(-gv)) * uv;
            }
            stg_cs_f2(out + (size_t)row * IHALF + col, o[0], o[1]);
            stg_cs_f2(out + (size_t)(row + 8) * IHALF + col, o[2], o[3]);
        }
    }
}

// ---------------- host launch ----------------
extern "C" void kernel_launch(void* const* d_in, const int* in_sizes, int n_in,
                              void* d_out, int out_size) {
    const float* x = (const float*)d_in[0];
    const float* w = (const float*)d_in[1];
    float* out = (float*)d_out;

    void* xh_ptr = nullptr;
    void* wh_ptr = nullptr;
    cudaGetSymbolAddress(&xh_ptr, g_xh);
    cudaGetSymbolAddress(&wh_ptr, g_wh);

    {
        int n8 = N8X + N8W;  // 20971520
        cvt_all_f16<<<n8 / 256, 256>>>((const float4*)x, (const float4*)w,
                                       (uint4*)xh_ptr, (uint4*)wh_ptr);
    }

    cudaFuncSetAttribute(teswiglu_gemm, cudaFuncAttributeMaxDynamicSharedMemorySize, SMEM_BYTES);
    int grid = NGRP * (MSPLIT / BM) * (IHALF / BN);  // 1536
    teswiglu_gemm<<<grid, 256, SMEM_BYTES>>>((const __half*)xh_ptr, (const __half*)wh_ptr, out);
}

// round 8
// speedup vs baseline: 1.1775x; 1.1014x over previous
#include <cuda_runtime.h>
#include <cuda_fp16.h>
#include <cstdint>

// ---------------- problem constants ----------------
#define HDIM   4096
#define MTOT   16384
#define NGRP   8
#define I2     3072
#define IHALF  1536
#define MSPLIT 2048

// ---------------- GEMM tiling ----------------
#define BM      128
#define BN      64              // output cols per CTA (gate AND up computed)
#define KC      64              // fp16 elems per K chunk (128 B rows)
#define NSTAGE  3
#define NITER   (HDIM / KC)     // 64

#define A_BYTES     (BM * KC * 2)              // 16384
#define B_BYTES     (2 * BN * KC * 2)          // 16384 (gate 64 rows + up 64 rows)
#define STAGE_BYTES (A_BYTES + B_BYTES)        // 32768
#define SMEM_BYTES  (NSTAGE * STAGE_BYTES)     // 98304 -> 2 CTAs/SM

// ---------------- fp16 scratch (device globals; no allocation) ----------------
__device__ __align__(1024) __half g_xh[(size_t)MTOT * HDIM];
__device__ __align__(1024) __half g_wh[(size_t)NGRP * I2 * HDIM];

#define N8X ((MTOT * HDIM) / 8)
#define N8W ((NGRP * I2 * HDIM) / 8)

// ---------------- helpers ----------------
__device__ __forceinline__ uint32_t smem_u32(const void* p) {
    uint32_t a;
    asm("{ .reg .u64 t; cvta.to.shared.u64 t, %1; cvt.u32.u64 %0, t; }" : "=r"(a) : "l"(p));
    return a;
}
__device__ __forceinline__ uint32_t swz(uint32_t o) {
    return o ^ ((o >> 3) & 0x70);
}
__device__ __forceinline__ void cp16(uint32_t s, const void* g) {
    asm volatile("cp.async.cg.shared.global [%0], [%1], 16;" :: "r"(s), "l"(g));
}
__device__ __forceinline__ void cp_commit() {
    asm volatile("cp.async.commit_group;" ::: "memory");
}
template <int N>
__device__ __forceinline__ void cp_wait() {
    asm volatile("cp.async.wait_group %0;" :: "n"(N) : "memory");
}
__device__ __forceinline__ void ldmx4(uint32_t* r, uint32_t addr) {
    asm volatile("ldmatrix.sync.aligned.m8n8.x4.shared.b16 {%0,%1,%2,%3}, [%4];"
                 : "=r"(r[0]), "=r"(r[1]), "=r"(r[2]), "=r"(r[3]) : "r"(addr));
}
__device__ __forceinline__ void mma16816(float* c, const uint32_t* a, const uint32_t* b) {
    asm volatile(
        "mma.sync.aligned.m16n8k16.row.col.f32.f16.f16.f32 "
        "{%0,%1,%2,%3}, {%4,%5,%6,%7}, {%8,%9}, {%0,%1,%2,%3};"
        : "+f"(c[0]), "+f"(c[1]), "+f"(c[2]), "+f"(c[3])
        : "r"(a[0]), "r"(a[1]), "r"(a[2]), "r"(a[3]), "r"(b[0]), "r"(b[1]));
}
__device__ __forceinline__ void stg_cs_f2(float* p, float a, float b) {
    asm volatile("st.global.cs.v2.f32 [%0], {%1,%2};" :: "l"(p), "f"(a), "f"(b) : "memory");
}

// ---------------- fp32 -> fp16 convert (x and w, streaming, 8 elems/thread) ----------------
__global__ void cvt_all_f16(const float4* __restrict__ x, const float4* __restrict__ w,
                            uint4* __restrict__ xh, uint4* __restrict__ wh) {
    int i = blockIdx.x * blockDim.x + threadIdx.x;
    const float4* in;
    uint4* out;
    int j;
    if (i < N8X) { in = x; out = xh; j = i; }
    else         { in = w; out = wh; j = i - N8X; if (j >= N8W) return; }
    float4 v0 = __ldcs(in + 2 * (size_t)j);
    float4 v1 = __ldcs(in + 2 * (size_t)j + 1);
    __half2 h0 = __floats2half2_rn(v0.x, v0.y);
    __half2 h1 = __floats2half2_rn(v0.z, v0.w);
    __half2 h2 = __floats2half2_rn(v1.x, v1.y);
    __half2 h3 = __floats2half2_rn(v1.z, v1.w);
    uint4 u;
    u.x = *reinterpret_cast<uint32_t*>(&h0);
    u.y = *reinterpret_cast<uint32_t*>(&h1);
    u.z = *reinterpret_cast<uint32_t*>(&h2);
    u.w = *reinterpret_cast<uint32_t*>(&h3);
    __stcs(out + j, u);
}

// ---------------- fused GEMM + SwiGLU (2 CTAs per SM) ----------------
// CTA tile: 128 rows x 64 output cols (gate + up both computed).
// 8 warps: wm = wid>>1 (4 x 32 rows), wn = wid&1 (2 x 32 cols).
// smem 96KB, regs <=128 -> 2 co-resident CTAs per SM hide each other's barriers.
__global__ void __launch_bounds__(256, 2)
teswiglu_gemm(const __half* __restrict__ xh, const __half* __restrict__ wh,
              float* __restrict__ out) {
    extern __shared__ __align__(128) char smem[];
    uint32_t sbase = smem_u32(smem);
    int tid = threadIdx.x;
    int wid = tid >> 5;
    int lid = tid & 31;

    int bid = blockIdx.x;
    int nt = bid % (IHALF / BN);                     // 24
    int mt = (bid / (IHALF / BN)) % (MSPLIT / BM);   // 16
    int g  = bid / ((IHALF / BN) * (MSPLIT / BM));

    const int m0 = g * MSPLIT + mt * BM;
    const __half* Ag = xh + (size_t)m0 * HDIM;
    const __half* Bg = wh + ((size_t)g * I2 + nt * BN) * HDIM;
    const __half* Bu = Bg + (size_t)IHALF * HDIM;

    // ---- one stage: A 128 rows + B 128 rows (gate 0-63, up 64-127) ----
    auto load_stage = [&](int s, int k0) {
        uint32_t st = sbase + s * STAGE_BYTES;
        #pragma unroll
        for (int c = 0; c < 4; c++) {
            int idx = tid + c * 256;
            int row = idx >> 3, seg = idx & 7;
            cp16(st + swz(row * 128 + seg * 16), Ag + (size_t)row * HDIM + k0 + seg * 8);
        }
        #pragma unroll
        for (int c = 0; c < 4; c++) {
            int idx = tid + c * 256;
            int row = idx >> 3, seg = idx & 7;   // 0..127
            const __half* src = (c < 2) ? (Bg + (size_t)row * HDIM)
                                        : (Bu + (size_t)(row - 64) * HDIM);
            cp16(st + A_BYTES + swz(row * 128 + seg * 16), src + k0 + seg * 8);
        }
        cp_commit();
    };

    #pragma unroll
    for (int s = 0; s < NSTAGE - 1; s++) load_stage(s, s * KC);

    const int wm = wid >> 1;      // 0..3 (32-row slabs)
    const int wn = wid & 1;       // 0..1 (2 x 32-col slabs)

    float cg[2][4][4];            // [mi][f][4]
    float cu[2][4][4];
    #pragma unroll
    for (int a = 0; a < 2; a++)
        #pragma unroll
        for (int b = 0; b < 4; b++)
            #pragma unroll
            for (int q = 0; q < 4; q++) { cg[a][b][q] = 0.f; cu[a][b][q] = 0.f; }

    const int la_row = (lid & 7) + ((lid >> 3) & 1) * 8;
    const int la_kb  = ((lid >> 4) & 1) * 16;
    const int lb_row = (lid & 7) + ((lid >> 4) & 1) * 8;
    const int lb_kb  = ((lid >> 3) & 1) * 16;

    int cs = 0;              // consume stage (rolling)
    int ls = NSTAGE - 1;     // next load stage (rolling)

    for (int it = 0; it < NITER; it++) {
        cp_wait<NSTAGE - 2>();
        __syncthreads();
        int jn = it + NSTAGE - 1;
        if (jn < NITER) {
            load_stage(ls, jn * KC);
            ls = (ls + 1 == NSTAGE) ? 0 : ls + 1;
        }

        uint32_t st = sbase + cs * STAGE_BYTES;
        cs = (cs + 1 == NSTAGE) ? 0 : cs + 1;
        uint32_t sA = st;
        uint32_t sB = st + A_BYTES;

        #pragma unroll
        for (int ki = 0; ki < 4; ki++) {
            uint32_t a[2][4];
            #pragma unroll
            for (int mi = 0; mi < 2; mi++) {
                int row = wm * 32 + mi * 16 + la_row;
                ldmx4(a[mi], sA + swz(row * 128 + ki * 32 + la_kb));
            }
            uint32_t bg[4][2], bu[4][2];
            #pragma unroll
            for (int nj = 0; nj < 2; nj++) {
                int rg = wn * 32 + nj * 16 + lb_row;
                uint32_t t0[4], t1[4];
                ldmx4(t0, sB + swz(rg * 128 + ki * 32 + lb_kb));
                ldmx4(t1, sB + swz((rg + 64) * 128 + ki * 32 + lb_kb));
                bg[2 * nj][0] = t0[0]; bg[2 * nj][1] = t0[1];
                bg[2 * nj + 1][0] = t0[2]; bg[2 * nj + 1][1] = t0[3];
                bu[2 * nj][0] = t1[0]; bu[2 * nj][1] = t1[1];
                bu[2 * nj + 1][0] = t1[2]; bu[2 * nj + 1][1] = t1[3];
            }
            #pragma unroll
            for (int mi = 0; mi < 2; mi++) {
                #pragma unroll
                for (int f = 0; f < 4; f++) {
                    mma16816(cg[mi][f], a[mi], bg[f]);
                    mma16816(cu[mi][f], a[mi], bu[f]);
                }
            }
        }
    }

    // ---- epilogue: silu(gate) * up, streaming fp32 stores ----
    #pragma unroll
    for (int mi = 0; mi < 2; mi++) {
        #pragma unroll
        for (int f = 0; f < 4; f++) {
            int row = m0 + wm * 32 + mi * 16 + (lid >> 2);
            int col = nt * BN + wn * 32 + f * 8 + 2 * (lid & 3);
            float o[4];
            #pragma unroll
            for (int q = 0; q < 4; q++) {
                float gv = cg[mi][f][q];
                float uv = cu[mi][f][q];
                o[q] = gv / (1.0f + __expf(-gv)) * uv;
            }
            stg_cs_f2(out + (size_t)row * IHALF + col, o[0], o[1]);
            stg_cs_f2(out + (size_t)(row + 8) * IHALF + col, o[2], o[3]);
        }
    }
}

// ---------------- host launch ----------------
extern "C" void kernel_launch(void* const* d_in, const int* in_sizes, int n_in,
                              void* d_out, int out_size) {
    const float* x = (const float*)d_in[0];
    const float* w = (const float*)d_in[1];
    float* out = (float*)d_out;

    void* xh_ptr = nullptr;
    void* wh_ptr = nullptr;
    cudaGetSymbolAddress(&xh_ptr, g_xh);
    cudaGetSymbolAddress(&wh_ptr, g_wh);

    {
        int n8 = N8X + N8W;
        cvt_all_f16<<<n8 / 256, 256>>>((const float4*)x, (const float4*)w,
                                       (uint4*)xh_ptr, (uint4*)wh_ptr);
    }

    cudaFuncSetAttribute(teswiglu_gemm, cudaFuncAttributeMaxDynamicSharedMemorySize, SMEM_BYTES);
    int grid = NGRP * (MSPLIT / BM) * (IHALF / BN);  // 8*16*24 = 3072
    teswiglu_gemm<<<grid, 256, SMEM_BYTES>>>((const __half*)xh_ptr, (const __half*)wh_ptr, out);
}